// round 8
// baseline (speedup 1.0000x reference)
#include <cuda_runtime.h>
#include <cstdint>

// Shapes (fixed by the problem)
#define B_ 16
#define T_ 32
#define NP_ 8
#define NG_ 4
#define J_ 14
#define H_ 256
#define BT_ (B_ * T_)              // 512
#define HM_ELEMS ((long long)BT_ * H_ * H_)   // 33,554,432
#define POSE_P (J_ * 3)            // 42 floats per joint-set

// accumulators: [0]=center SSE, [1]=offset sum, [2]=size sum, [3]=pose sum
__device__ double g_acc[4];

__global__ void init_kernel() {
    if (threadIdx.x < 4) g_acc[threadIdx.x] = 0.0;
}

// ---------------------------------------------------------------------------
// Kernel 1: big MSE reduction (HBM-bound, float4 vectorized)
// hor_heatmap is (B,T,1,H,H) contiguous == gt_heatmap (B,T,H,H) layout.
// ---------------------------------------------------------------------------
__global__ __launch_bounds__(256) void center_kernel(
    const float4* __restrict__ a, const float4* __restrict__ b, long long n4)
{
    float s = 0.0f;
    long long stride = (long long)gridDim.x * blockDim.x;
    for (long long i = (long long)blockIdx.x * blockDim.x + threadIdx.x; i < n4; i += stride) {
        float4 x = __ldg(a + i);
        float4 y = __ldg(b + i);
        float d0 = x.x - y.x, d1 = x.y - y.y, d2 = x.z - y.z, d3 = x.w - y.w;
        s += d0 * d0 + d1 * d1 + d2 * d2 + d3 * d3;
    }
    // warp reduce
    for (int o = 16; o; o >>= 1) s += __shfl_down_sync(0xffffffffu, s, o);
    __shared__ float sh[8];
    int lane = threadIdx.x & 31, wid = threadIdx.x >> 5;
    if (lane == 0) sh[wid] = s;
    __syncthreads();
    if (wid == 0) {
        s = (lane < (blockDim.x >> 5)) ? sh[lane] : 0.0f;
        for (int o = 4; o; o >>= 1) s += __shfl_down_sync(0xffffffffu, s, o);
        if (lane == 0) atomicAdd(&g_acc[0], (double)s);
    }
}

// ---------------------------------------------------------------------------
// Kernel 2: per-(b,t) Hungarian (brute-force over 1680 injective maps)
// one warp (32 threads) per bt cell
// ---------------------------------------------------------------------------
__global__ __launch_bounds__(32) void match_kernel(
    const float* __restrict__ hor_offset,   // [BT, NP, 2]
    const float* __restrict__ hor_bsize,    // [BT, NP, 4]
    const float* __restrict__ hor_center,   // [BT, NP, 2]
    const float* __restrict__ scores,       // [BT, NP]
    const float* __restrict__ x_pose3d,     // [BT, NP, 42]
    const float* __restrict__ gt_wh,        // [BT, NG, 4]
    const float* __restrict__ gt_off,       // [BT, NG, 2]
    const float* __restrict__ gt_center,    // [BT, NG, 2]
    const float* __restrict__ gt_pose)      // [BT, NG, 42]
{
    const int bt = blockIdx.x;
    const int tid = threadIdx.x;

    __shared__ float spp[NP_ * POSE_P];   // 336
    __shared__ float sgp[NG_ * POSE_P];   // 168
    __shared__ float spc[NP_ * 2], sgc[NG_ * 2], ssc[NP_];
    __shared__ float spo[NP_ * 2], sgo[NG_ * 2];
    __shared__ float sps[NP_ * 4], sgs[NG_ * 4];
    __shared__ float cB[NP_ * NG_], cP[NP_ * NG_];

    // cooperative loads
    for (int k = tid; k < NP_ * POSE_P; k += 32) spp[k] = __ldg(x_pose3d + (long long)bt * NP_ * POSE_P + k);
    for (int k = tid; k < NG_ * POSE_P; k += 32) sgp[k] = __ldg(gt_pose + (long long)bt * NG_ * POSE_P + k);
    if (tid < NP_ * 2) spc[tid] = __ldg(hor_center + bt * NP_ * 2 + tid);
    if (tid < NG_ * 2) sgc[tid] = __ldg(gt_center + bt * NG_ * 2 + tid);
    if (tid < NP_)     ssc[tid] = __ldg(scores + bt * NP_ + tid);
    if (tid < NP_ * 2) spo[tid] = __ldg(hor_offset + bt * NP_ * 2 + tid);
    if (tid < NG_ * 2) sgo[tid] = __ldg(gt_off + bt * NG_ * 2 + tid);
    for (int k = tid; k < NP_ * 4; k += 32) sps[k] = __ldg(hor_bsize + bt * NP_ * 4 + k);
    if (tid < NG_ * 4) sgs[tid] = __ldg(gt_wh + bt * NG_ * 4 + tid);
    __syncthreads();

    // cost matrices: lane l -> (pred i = l/4, gt j = l%4)
    {
        int i = tid >> 2, j = tid & 3;
        float dx = spc[2 * i] - sgc[2 * j];
        float dy = spc[2 * i + 1] - sgc[2 * j + 1];
        cB[tid] = sqrtf(dx * dx + dy * dy) - ssc[i];
        float s = 0.0f;
#pragma unroll
        for (int k = 0; k < POSE_P; k++) {
            float d = spp[i * POSE_P + k] - sgp[j * POSE_P + k];
            s += d * d;
        }
        cP[tid] = sqrtf(s);
    }
    __syncthreads();

    // enumerate tuples (i0,i1,i2,i3) in 8^4 lexicographic order; skip non-injective.
    // linear index order == itertools.permutations order among injective tuples.
    float bestB = 3.0e38f, bestP = 3.0e38f;
    int ibB = 0, ibP = 0;
    for (int t = tid; t < 4096; t += 32) {
        int i3 = t & 7, i2 = (t >> 3) & 7, i1 = (t >> 6) & 7, i0 = (t >> 9) & 7;
        if (i0 == i1 || i0 == i2 || i0 == i3 || i1 == i2 || i1 == i3 || i2 == i3) continue;
        float vb = cB[i0 * 4 + 0] + cB[i1 * 4 + 1] + cB[i2 * 4 + 2] + cB[i3 * 4 + 3];
        float vp = cP[i0 * 4 + 0] + cP[i1 * 4 + 1] + cP[i2 * 4 + 2] + cP[i3 * 4 + 3];
        if (vb < bestB) { bestB = vb; ibB = t; }   // strictly < keeps earliest t within lane
        if (vp < bestP) { bestP = vp; ibP = t; }
    }
    // warp argmin with lexicographic tie-break (smaller t wins)
    for (int o = 16; o; o >>= 1) {
        float vb = __shfl_down_sync(0xffffffffu, bestB, o);
        int jb = __shfl_down_sync(0xffffffffu, ibB, o);
        if (vb < bestB || (vb == bestB && jb < ibB)) { bestB = vb; ibB = jb; }
        float vp = __shfl_down_sync(0xffffffffu, bestP, o);
        int jp = __shfl_down_sync(0xffffffffu, ibP, o);
        if (vp < bestP || (vp == bestP && jp < ibP)) { bestP = vp; ibP = jp; }
    }
    ibB = __shfl_sync(0xffffffffu, ibB, 0);
    ibP = __shfl_sync(0xffffffffu, ibP, 0);

    // losses for chosen assignments; lanes 0..3 each handle one gt column j
    if (tid < NG_) {
        int j = tid;
        int rB = (ibB >> (3 * (3 - j))) & 7;
        int rP = (ibP >> (3 * (3 - j))) & 7;

        float off = 0.5f * (fabsf(spo[2 * rB]     - sgo[2 * j]) +
                            fabsf(spo[2 * rB + 1] - sgo[2 * j + 1]));
        float siz = 0.25f * (fabsf(sps[4 * rB + 0] - sgs[4 * j + 0]) +
                             fabsf(sps[4 * rB + 1] - sgs[4 * j + 1]) +
                             fabsf(sps[4 * rB + 2] - sgs[4 * j + 2]) +
                             fabsf(sps[4 * rB + 3] - sgs[4 * j + 3]));
        float pose = 0.0f;
#pragma unroll
        for (int k = 0; k < POSE_P; k++) {
            float d = spp[rP * POSE_P + k] - sgp[j * POSE_P + k];
            pose += d * d;
        }
        atomicAdd(&g_acc[1], (double)off);
        atomicAdd(&g_acc[2], (double)siz);
        atomicAdd(&g_acc[3], (double)pose);
    }
}

__global__ void finalize_kernel(float* out) {
    if (threadIdx.x == 0) {
        double center = g_acc[0] / (double)HM_ELEMS;
        double off    = g_acc[1] / (double)BT_;
        double siz    = g_acc[2] / (double)BT_;
        double pose   = g_acc[3] / ((double)BT_ * NP_ * J_);
        out[0] = (float)(center + off + siz + pose);   // GAMMA = 1.0
    }
}

extern "C" void kernel_launch(void* const* d_in, const int* in_sizes, int n_in,
                              void* d_out, int out_size)
{
    const float* hor_heatmap = (const float*)d_in[0];  // [B,T,1,H,H]
    const float* hor_offset  = (const float*)d_in[1];  // [B,T,NP,2]
    const float* hor_bsize   = (const float*)d_in[2];  // [B,T,NP,4]
    const float* hor_center  = (const float*)d_in[3];  // [B,T,NP,2]
    const float* scores      = (const float*)d_in[4];  // [B,T,NP]
    const float* x_pose3d    = (const float*)d_in[5];  // [B,T,NP,J,3]
    const float* gt_heatmap  = (const float*)d_in[6];  // [B,T,H,H]
    const float* gt_wh       = (const float*)d_in[7];  // [B,T,NG,4]
    const float* gt_off      = (const float*)d_in[8];  // [B,T,NG,2]
    const float* gt_center   = (const float*)d_in[9];  // [B,T,NG,2]
    const float* gt_pose     = (const float*)d_in[10]; // [B,T,NG,J,3]
    float* out = (float*)d_out;

    init_kernel<<<1, 32>>>();

    long long n4 = HM_ELEMS / 4;   // 8,388,608 float4s
    center_kernel<<<1184, 256>>>((const float4*)hor_heatmap,
                                 (const float4*)gt_heatmap, n4);

    match_kernel<<<BT_, 32>>>(hor_offset, hor_bsize, hor_center, scores, x_pose3d,
                              gt_wh, gt_off, gt_center, gt_pose);

    finalize_kernel<<<1, 32>>>(out);
}

// round 9
// speedup vs baseline: 1.3303x; 1.3303x over previous
#include <cuda_runtime.h>
#include <cstdint>

// Shapes (fixed by the problem)
#define B_ 16
#define T_ 32
#define NP_ 8
#define NG_ 4
#define J_ 14
#define H_ 256
#define BT_ (B_ * T_)                        // 512
#define HM_ELEMS ((long long)BT_ * H_ * H_)  // 33,554,432
#define POSE_P (J_ * 3)                      // 42
#define NBLK 1184                            // 148 SMs * 8 blocks (256 thr) = full chip, 1 wave

// No-init scratch: every slot is written unconditionally each launch.
__device__ float    g_center_partial[NBLK];
__device__ float    g_match_partial[BT_];
__device__ unsigned g_count = 0;   // reset to 0 by the finalizing block each launch

__global__ __launch_bounds__(256) void fused_kernel(
    const float4* __restrict__ hm_a,        // hor_heatmap[:,:,0] as float4
    const float4* __restrict__ hm_b,        // gt_heatmap as float4
    const float*  __restrict__ hor_offset,  // [BT, NP, 2]
    const float*  __restrict__ hor_bsize,   // [BT, NP, 4]
    const float*  __restrict__ hor_center,  // [BT, NP, 2]
    const float*  __restrict__ scores,      // [BT, NP]
    const float*  __restrict__ x_pose3d,    // [BT, NP, 42]
    const float*  __restrict__ gt_wh,       // [BT, NG, 4]
    const float*  __restrict__ gt_off,      // [BT, NG, 2]
    const float*  __restrict__ gt_center,   // [BT, NG, 2]
    const float*  __restrict__ gt_pose,     // [BT, NG, 42]
    float* __restrict__ out)
{
    const int tid  = threadIdx.x;
    const int lane = tid & 31;
    const int wid  = tid >> 5;
    const long long n4     = HM_ELEMS / 4;                       // 8,388,608
    const long long stride = (long long)gridDim.x * blockDim.x;  // 303,104

    // ---------------- center MSE: grid-stride, 4-way unrolled (MLP = 8 LDG.128) --
    float s = 0.0f;
    long long i = (long long)blockIdx.x * blockDim.x + tid;
    for (; i + 3 * stride < n4; i += 4 * stride) {
        float4 a0 = hm_a[i];              float4 b0 = hm_b[i];
        float4 a1 = hm_a[i + stride];     float4 b1 = hm_b[i + stride];
        float4 a2 = hm_a[i + 2 * stride]; float4 b2 = hm_b[i + 2 * stride];
        float4 a3 = hm_a[i + 3 * stride]; float4 b3 = hm_b[i + 3 * stride];
        float d;
        d = a0.x - b0.x; s += d * d;  d = a0.y - b0.y; s += d * d;
        d = a0.z - b0.z; s += d * d;  d = a0.w - b0.w; s += d * d;
        d = a1.x - b1.x; s += d * d;  d = a1.y - b1.y; s += d * d;
        d = a1.z - b1.z; s += d * d;  d = a1.w - b1.w; s += d * d;
        d = a2.x - b2.x; s += d * d;  d = a2.y - b2.y; s += d * d;
        d = a2.z - b2.z; s += d * d;  d = a2.w - b2.w; s += d * d;
        d = a3.x - b3.x; s += d * d;  d = a3.y - b3.y; s += d * d;
        d = a3.z - b3.z; s += d * d;  d = a3.w - b3.w; s += d * d;
    }
    for (; i < n4; i += stride) {
        float4 a0 = hm_a[i]; float4 b0 = hm_b[i];
        float d;
        d = a0.x - b0.x; s += d * d;  d = a0.y - b0.y; s += d * d;
        d = a0.z - b0.z; s += d * d;  d = a0.w - b0.w; s += d * d;
    }
    // warp partials
    for (int o = 16; o; o >>= 1) s += __shfl_down_sync(0xffffffffu, s, o);
    __shared__ float shC[8];
    if (lane == 0) shC[wid] = s;

    // ---------------- match data loads (blocks 0..511), overlapped with HBM tail --
    const bool do_match = (blockIdx.x < BT_);
    const int  bt = blockIdx.x;

    __shared__ float spp[NP_ * POSE_P];   // 336
    __shared__ float sgp[NG_ * POSE_P];   // 168
    __shared__ float spc[NP_ * 2], sgc[NG_ * 2], ssc[NP_];
    __shared__ float spo[NP_ * 2], sgo[NG_ * 2];
    __shared__ float sps[NP_ * 4], sgs[NG_ * 4];
    __shared__ float cB[NP_ * NG_], cP[NP_ * NG_];
    __shared__ bool  sh_last;

    if (do_match) {
        for (int k = tid; k < NP_ * POSE_P; k += 256) spp[k] = x_pose3d[(long long)bt * NP_ * POSE_P + k];
        for (int k = tid; k < NG_ * POSE_P; k += 256) sgp[k] = gt_pose[(long long)bt * NG_ * POSE_P + k];
        if (tid < NP_ * 2) spc[tid] = hor_center[bt * NP_ * 2 + tid];
        if (tid < NG_ * 2) sgc[tid] = gt_center[bt * NG_ * 2 + tid];
        if (tid < NP_)     ssc[tid] = scores[bt * NP_ + tid];
        if (tid < NP_ * 2) spo[tid] = hor_offset[bt * NP_ * 2 + tid];
        if (tid < NG_ * 2) sgo[tid] = gt_off[bt * NG_ * 2 + tid];
        if (tid < NP_ * 4) sps[tid] = hor_bsize[bt * NP_ * 4 + tid];
        if (tid < NG_ * 4) sgs[tid] = gt_wh[bt * NG_ * 4 + tid];
    }
    __syncthreads();   // covers shC and match smem

    // ---------------- warp 0: finish center reduce, then do the match ------------
    if (wid == 0) {
        float cs = (lane < 8) ? shC[lane] : 0.0f;
        for (int o = 4; o; o >>= 1) cs += __shfl_down_sync(0xffffffffu, cs, o);
        // lane 0 now holds the block's center partial; keep it in-register

        float match_total = 0.0f;
        if (do_match) {
            // cost matrices: lane l -> (pred i = l/4, gt j = l%4)
            {
                int pi = lane >> 2, gj = lane & 3;
                float dx = spc[2 * pi]     - sgc[2 * gj];
                float dy = spc[2 * pi + 1] - sgc[2 * gj + 1];
                cB[lane] = sqrtf(dx * dx + dy * dy) - ssc[pi];
                float ps = 0.0f;
#pragma unroll
                for (int k = 0; k < POSE_P; k++) {
                    float dd = spp[pi * POSE_P + k] - sgp[gj * POSE_P + k];
                    ps += dd * dd;
                }
                cP[lane] = sqrtf(ps);
            }
            __syncwarp();

            // enumerate 8^4 tuples in lexicographic order (== permutations order
            // among injective tuples); skip non-injective.
            float bestB = 3.0e38f, bestP = 3.0e38f;
            int ibB = 0, ibP = 0;
            for (int t = lane; t < 4096; t += 32) {
                int i3 = t & 7, i2 = (t >> 3) & 7, i1 = (t >> 6) & 7, i0 = (t >> 9) & 7;
                if (i0 == i1 || i0 == i2 || i0 == i3 || i1 == i2 || i1 == i3 || i2 == i3) continue;
                float vb = cB[i0 * 4 + 0] + cB[i1 * 4 + 1] + cB[i2 * 4 + 2] + cB[i3 * 4 + 3];
                float vp = cP[i0 * 4 + 0] + cP[i1 * 4 + 1] + cP[i2 * 4 + 2] + cP[i3 * 4 + 3];
                if (vb < bestB) { bestB = vb; ibB = t; }
                if (vp < bestP) { bestP = vp; ibP = t; }
            }
            for (int o = 16; o; o >>= 1) {
                float vb = __shfl_down_sync(0xffffffffu, bestB, o);
                int   jb = __shfl_down_sync(0xffffffffu, ibB, o);
                if (vb < bestB || (vb == bestB && jb < ibB)) { bestB = vb; ibB = jb; }
                float vp = __shfl_down_sync(0xffffffffu, bestP, o);
                int   jp = __shfl_down_sync(0xffffffffu, ibP, o);
                if (vp < bestP || (vp == bestP && jp < ibP)) { bestP = vp; ibP = jp; }
            }
            ibB = __shfl_sync(0xffffffffu, ibB, 0);
            ibP = __shfl_sync(0xffffffffu, ibP, 0);

            // per-gt losses on lanes 0..3; combine into one scalar per bt
            float val = 0.0f;
            if (lane < NG_) {
                int j  = lane;
                int rB = (ibB >> (3 * (3 - j))) & 7;
                int rP = (ibP >> (3 * (3 - j))) & 7;
                float off = 0.5f * (fabsf(spo[2 * rB]     - sgo[2 * j]) +
                                    fabsf(spo[2 * rB + 1] - sgo[2 * j + 1]));
                float siz = 0.25f * (fabsf(sps[4 * rB + 0] - sgs[4 * j + 0]) +
                                     fabsf(sps[4 * rB + 1] - sgs[4 * j + 1]) +
                                     fabsf(sps[4 * rB + 2] - sgs[4 * j + 2]) +
                                     fabsf(sps[4 * rB + 3] - sgs[4 * j + 3]));
                float pose = 0.0f;
#pragma unroll
                for (int k = 0; k < POSE_P; k++) {
                    float dd = spp[rP * POSE_P + k] - sgp[j * POSE_P + k];
                    pose += dd * dd;
                }
                val = off + siz + pose * (1.0f / (float)(NP_ * J_));
            }
            val += __shfl_down_sync(0xffffffffu, val, 2);
            val += __shfl_down_sync(0xffffffffu, val, 1);
            match_total = val;   // lane 0 holds the per-bt total
        }

        if (lane == 0) {
            g_center_partial[blockIdx.x] = cs;
            if (do_match) g_match_partial[bt] = match_total;
            __threadfence();
            unsigned r = atomicAdd(&g_count, 1u);
            sh_last = (r == (unsigned)(gridDim.x - 1));
        }
    }
    __syncthreads();

    // ---------------- last block finalizes (and resets the counter) --------------
    if (sh_last) {
        __threadfence();
        double c = 0.0, m = 0.0;
        for (int k = tid; k < NBLK; k += 256) c += (double)g_center_partial[k];
        for (int k = tid; k < BT_;  k += 256) m += (double)g_match_partial[k];
        for (int o = 16; o; o >>= 1) {
            c += __shfl_down_sync(0xffffffffu, c, o);
            m += __shfl_down_sync(0xffffffffu, m, o);
        }
        __shared__ double shc[8], shm[8];
        if (lane == 0) { shc[wid] = c; shm[wid] = m; }
        __syncthreads();
        if (wid == 0) {
            c = (lane < 8) ? shc[lane] : 0.0;
            m = (lane < 8) ? shm[lane] : 0.0;
            for (int o = 4; o; o >>= 1) {
                c += __shfl_down_sync(0xffffffffu, c, o);
                m += __shfl_down_sync(0xffffffffu, m, o);
            }
            if (lane == 0) {
                out[0] = (float)(c / (double)HM_ELEMS + m / (double)BT_);  // GAMMA = 1
                g_count = 0;   // deterministic across graph replays
            }
        }
    }
}

extern "C" void kernel_launch(void* const* d_in, const int* in_sizes, int n_in,
                              void* d_out, int out_size)
{
    const float* hor_heatmap = (const float*)d_in[0];  // [B,T,1,H,H]
    const float* hor_offset  = (const float*)d_in[1];  // [B,T,NP,2]
    const float* hor_bsize   = (const float*)d_in[2];  // [B,T,NP,4]
    const float* hor_center  = (const float*)d_in[3];  // [B,T,NP,2]
    const float* scores      = (const float*)d_in[4];  // [B,T,NP]
    const float* x_pose3d    = (const float*)d_in[5];  // [B,T,NP,J,3]
    const float* gt_heatmap  = (const float*)d_in[6];  // [B,T,H,H]
    const float* gt_wh       = (const float*)d_in[7];  // [B,T,NG,4]
    const float* gt_off      = (const float*)d_in[8];  // [B,T,NG,2]
    const float* gt_center   = (const float*)d_in[9];  // [B,T,NG,2]
    const float* gt_pose     = (const float*)d_in[10]; // [B,T,NG,J,3]
    float* out = (float*)d_out;

    fused_kernel<<<NBLK, 256>>>(
        (const float4*)hor_heatmap, (const float4*)gt_heatmap,
        hor_offset, hor_bsize, hor_center, scores, x_pose3d,
        gt_wh, gt_off, gt_center, gt_pose, out);
}